// round 17
// baseline (speedup 1.0000x reference)
#include <cuda_runtime.h>
#include <cuda_bf16.h>
#include <math.h>

#define BB 4
#define CC 64
#define CI 16
#define PP 4096
#define NCOL 128
#define TP 128
#define NT (PP/TP)
#define LOG2E 1.4426950408889634f
#define ONES16 0x3F803F80u

// ---------------- scratch (device globals; no allocations allowed) ----------
__device__ float    g_q[BB*CI*PP];       // [b][o][p]  fp32
__device__ float    g_k[BB*CI*PP];       // [b][o][p]  fp32
__device__ unsigned g_v32[BB*CC*PP/2];   // [b][c][p/2] packed bf16x2
__device__ float    g_out[BB*CC*PP];     // pre-gate output
__device__ float    g_sum[BB*CC];
__device__ unsigned g_maxk[BB*CC];

__device__ __forceinline__ unsigned fkey(float f) {
    unsigned u = __float_as_uint(f);
    return (u & 0x80000000u) ? ~u : (u | 0x80000000u);
}
__device__ __forceinline__ float funkey(unsigned k) {
    unsigned u = (k & 0x80000000u) ? (k & 0x7FFFFFFFu) : ~k;
    return __uint_as_float(u);
}

// ---------------- cvt / mma / cp.async helpers --------------------------------
__device__ __forceinline__ unsigned tf32cvt(float f) {
    unsigned r;
    asm("cvt.rna.tf32.f32 %0, %1;" : "=r"(r) : "f"(f));
    return r;
}
__device__ __forceinline__ unsigned bf16x2pack(float hi, float lo) {
    unsigned r;
    asm("cvt.rn.bf16x2.f32 %0, %1, %2;" : "=r"(r) : "f"(hi), "f"(lo));
    return r;
}
__device__ __forceinline__ float ex2(float x) {
    float y;
    asm("ex2.approx.f32 %0, %1;" : "=f"(y) : "f"(x));
    return y;
}
__device__ __forceinline__ void mma8(float c[4],
                                     unsigned a0, unsigned a1, unsigned a2, unsigned a3,
                                     unsigned b0, unsigned b1)
{
    asm volatile(
        "mma.sync.aligned.m16n8k8.row.col.f32.tf32.tf32.f32 "
        "{%0,%1,%2,%3},{%4,%5,%6,%7},{%8,%9},{%0,%1,%2,%3};"
        : "+f"(c[0]), "+f"(c[1]), "+f"(c[2]), "+f"(c[3])
        : "r"(a0), "r"(a1), "r"(a2), "r"(a3), "r"(b0), "r"(b1));
}
__device__ __forceinline__ void mma16(float c[4],
                                      unsigned a0, unsigned a1, unsigned a2, unsigned a3,
                                      unsigned b0, unsigned b1)
{
    asm volatile(
        "mma.sync.aligned.m16n8k16.row.col.f32.bf16.bf16.f32 "
        "{%0,%1,%2,%3},{%4,%5,%6,%7},{%8,%9},{%0,%1,%2,%3};"
        : "+f"(c[0]), "+f"(c[1]), "+f"(c[2]), "+f"(c[3])
        : "r"(a0), "r"(a1), "r"(a2), "r"(a3), "r"(b0), "r"(b1));
}
__device__ __forceinline__ void cp16(void* dst, const void* src) {
    unsigned ds = (unsigned)__cvta_generic_to_shared(dst);
    asm volatile("cp.async.cg.shared.global [%0], [%1], 16;" :: "r"(ds), "l"(src));
}
__device__ __forceinline__ unsigned sm_u32(const void* p) {
    return (unsigned)__cvta_generic_to_shared(p);
}

// ---------------- K1: q/k/v projections, tensor cores, async staging ---------
#define WS 68     // W smem row stride (floats)
#define XS 72     // X smem row stride (floats)
__global__ void __launch_bounds__(384)
qkv_kernel(const float* __restrict__ ftr,
           const float* __restrict__ wq, const float* __restrict__ bq,
           const float* __restrict__ wk, const float* __restrict__ bk,
           const float* __restrict__ wv, const float* __restrict__ bv)
{
    __shared__ float wt[96*WS];
    __shared__ float xs[64*XS];
    __shared__ float bs[96];

    int tid = threadIdx.x;
    int b   = blockIdx.y;
    int p0  = blockIdx.x * 64;

    for (int f = tid; f < 256; f += 384) {
        int row = f >> 4, s = f & 15;
        cp16(&wt[row*WS + s*4], wq + row*64 + s*4);
    }
    for (int f = tid; f < 256; f += 384) {
        int row = f >> 4, s = f & 15;
        cp16(&wt[(16 + row)*WS + s*4], wk + row*64 + s*4);
    }
    for (int f = tid; f < 1024; f += 384) {
        int row = f >> 4, s = f & 15;
        cp16(&wt[(32 + row)*WS + s*4], wv + row*64 + s*4);
    }
    for (int f = tid; f < 1024; f += 384) {
        int c = f >> 4, s = f & 15;
        cp16(&xs[c*XS + s*4], ftr + ((size_t)b*CC + c)*PP + p0 + s*4);
    }
    asm volatile("cp.async.commit_group;");

    if (tid < 16) bs[tid] = bq[tid];
    else if (tid < 32) bs[tid] = bk[tid - 16];
    else if (tid < 96) bs[tid] = bv[tid - 32];
    if (blockIdx.x == 0 && blockIdx.y == 0 && tid < BB*CC) {
        g_sum[tid] = 0.0f;
        g_maxk[tid] = 0u;
    }
    asm volatile("cp.async.wait_group 0;");
    __syncthreads();

    int w = tid >> 5;
    int lane = tid & 31, r = lane >> 2, q4 = lane & 3;
    int mb = w >> 1, nh = w & 1;
    int m0 = mb * 16, n0 = nh * 32;

    unsigned a[8][4];
#pragma unroll
    for (int ks = 0; ks < 8; ks++) {
        a[ks][0] = __float_as_uint(wt[(m0 + r    )*WS + ks*8 + q4]);
        a[ks][1] = __float_as_uint(wt[(m0 + r + 8)*WS + ks*8 + q4]);
        a[ks][2] = __float_as_uint(wt[(m0 + r    )*WS + ks*8 + q4 + 4]);
        a[ks][3] = __float_as_uint(wt[(m0 + r + 8)*WS + ks*8 + q4 + 4]);
    }

    float c8[4][4];
#pragma unroll
    for (int nb = 0; nb < 4; nb++)
#pragma unroll
        for (int k2 = 0; k2 < 4; k2++) c8[nb][k2] = 0.0f;

#pragma unroll
    for (int ks = 0; ks < 8; ks++)
#pragma unroll
        for (int nb = 0; nb < 4; nb++) {
            unsigned b0 = __float_as_uint(xs[(ks*8 + q4    )*XS + n0 + nb*8 + r]);
            unsigned b1 = __float_as_uint(xs[(ks*8 + q4 + 4)*XS + n0 + nb*8 + r]);
            mma8(c8[nb], a[ks][0], a[ks][1], a[ks][2], a[ks][3], b0, b1);
        }

    float bias0 = bs[m0 + r], bias1 = bs[m0 + r + 8];
#pragma unroll
    for (int nb = 0; nb < 4; nb++) {
        int col = p0 + n0 + nb*8 + q4*2;
        int row0 = m0 + r, row1 = m0 + r + 8;
        float v00 = c8[nb][0] + bias0, v01 = c8[nb][1] + bias0;
        float v10 = c8[nb][2] + bias1, v11 = c8[nb][3] + bias1;
        if (row0 < 16) {
            *reinterpret_cast<float2*>(&g_q[((size_t)b*CI + row0)*PP + col]) = make_float2(v00, v01);
            *reinterpret_cast<float2*>(&g_q[((size_t)b*CI + row1)*PP + col]) = make_float2(v10, v11);
        } else if (row0 < 32) {
            *reinterpret_cast<float2*>(&g_k[((size_t)b*CI + row0 - 16)*PP + col]) = make_float2(v00, v01);
            *reinterpret_cast<float2*>(&g_k[((size_t)b*CI + row1 - 16)*PP + col]) = make_float2(v10, v11);
        } else {
            g_v32[(((size_t)b*CC + row0 - 32)*PP + col) >> 1] = bf16x2pack(v01, v00);
            g_v32[(((size_t)b*CC + row1 - 32)*PP + col) >> 1] = bf16x2pack(v11, v10);
        }
    }
}

// ---------------- K2: flash attention, no k-split, 2 CTAs/SM -----------------
#define KT 20     // kkT row stride (u32)
#define QT 136    // qqT row stride (u32)
#define VS 68     // vv row stride (u32)

struct SmemB {
    unsigned kkT[NCOL*KT];      // 10.2 KB
    unsigned qqT[3][16*QT];     // 26.1 KB
    unsigned vv[3][64*VS];      // 52.2 KB
    float wsum[8][64];          // 2 KB
    float wmax[8][64];          // 2 KB
};                              // ~92.7 KB -> 2 CTAs/SM

extern __shared__ char smem_raw[];

__device__ __forceinline__ void stage_qv(SmemB& sm, int buf, int b, int p0, int tid)
{
    // Q: 16 x 128 fp32 = 512 float4, 2 per thread
#pragma unroll
    for (int u = 0; u < 2; u++) {
        int fidx = tid + u*256;
        int o = fidx >> 5, p4 = fidx & 31;
        cp16(&sm.qqT[buf][o*QT + p4*4],
             g_q + ((size_t)b*CI + o)*PP + p0 + p4*4);
    }
    // V: 64 x 64 u32 = 1024 uint4, 4 per thread
    const unsigned* vbase = g_v32 + ((size_t)b*CC*PP >> 1) + (p0 >> 1);
#pragma unroll
    for (int rr = 0; rr < 4; rr++) {
        int fidx = rr*256 + tid;
        int row = fidx >> 4, c4 = fidx & 15;
        cp16(&sm.vv[buf][row*VS + c4*4],
             vbase + (size_t)row*(PP/2) + c4*4);
    }
}

// grid (PP/NCOL, BB), 256 threads (8 warps): warp jb = w, full p per warp
__global__ void __launch_bounds__(256, 2)
attn_kernel(const float* __restrict__ ftr, const float* __restrict__ delta)
{
    SmemB& sm = *reinterpret_cast<SmemB*>(smem_raw);
    int tid  = threadIdx.x;
    int w    = tid >> 5;
    int lane = tid & 31;
    int r    = lane >> 2;
    int q4   = lane & 3;
    int b    = blockIdx.y;
    int col0 = blockIdx.x * NCOL;

    int jb = w;
    int j0 = jb*16 + r;
    int j1 = j0 + 8;

    stage_qv(sm, 0, b, 0, tid);
    asm volatile("cp.async.commit_group;");
    stage_qv(sm, 1, b, TP, tid);
    asm volatile("cp.async.commit_group;");

    for (int i = tid; i < 16*NCOL; i += 256) {
        int o = i >> 7, jj = i & 127;
        sm.kkT[jj*KT + o] = tf32cvt(g_k[((size_t)(b*CI + o))*PP + col0 + jj] * LOG2E);
    }
    __syncthreads();

    unsigned ka[2][4];
#pragma unroll
    for (int ks = 0; ks < 2; ks++) {
        ka[ks][0] = sm.kkT[(jb*16 + r    )*KT + ks*8 + q4];
        ka[ks][1] = sm.kkT[(jb*16 + r + 8)*KT + ks*8 + q4];
        ka[ks][2] = sm.kkT[(jb*16 + r    )*KT + ks*8 + q4 + 4];
        ka[ks][3] = sm.kkT[(jb*16 + r + 8)*KT + ks*8 + q4 + 4];
    }

    unsigned vv_lane = sm_u32(&sm.vv[0][0])
        + ((((lane >> 4)*8 + (lane & 7))*VS + ((lane >> 3) & 1)*4) << 2);

    float cacc[8][4];
#pragma unroll
    for (int nb = 0; nb < 8; nb++)
#pragma unroll
        for (int k2 = 0; k2 < 4; k2++) cacc[nb][k2] = 0.0f;
    float lcc[4] = {0.0f, 0.0f, 0.0f, 0.0f};

    for (int t = 0; t < NT; t++) {
        if (t + 1 < NT) asm volatile("cp.async.wait_group 1;");
        else            asm volatile("cp.async.wait_group 0;");
        __syncthreads();

        if (t + 2 < NT) {
            stage_qv(sm, (t + 2) % 3, b, (t + 2)*TP, tid);
            asm volatile("cp.async.commit_group;");
        }
        int buf = t % 3;
        unsigned vbuf = vv_lane + buf*(64*VS*4);
        const unsigned* qq = &sm.qqT[buf][0];

        // rolling score buffers, 8 chunks cover full p=128
        float srP[2][2][4];
        auto mma1_pair = [&](int c, int pp) {
#pragma unroll
            for (int u = 0; u < 2; u++) {
                int nb = 2*c + u;
                int pbase = nb*8 + r;
                unsigned b00 = qq[(q4     )*QT + pbase];
                unsigned b01 = qq[(q4 + 4 )*QT + pbase];
                unsigned b10 = qq[(8 + q4 )*QT + pbase];
                unsigned b11 = qq[(12 + q4)*QT + pbase];
                float* s = srP[pp][u];
                s[0] = s[1] = s[2] = s[3] = 0.0f;
                mma8(s, ka[0][0], ka[0][1], ka[0][2], ka[0][3], b00, b01);
                mma8(s, ka[1][0], ka[1][1], ka[1][2], ka[1][3], b10, b11);
            }
        };

        mma1_pair(0, 0);
#pragma unroll
        for (int c = 0; c < 8; c++) {
            int cur = c & 1;
            if (c < 7) mma1_pair(c + 1, cur ^ 1);

            const float* sA = srP[cur][0];
            const float* sB = srP[cur][1];
            float eA0 = ex2(sA[0]);
            float eA1 = ex2(sA[1]);
            float eA2 = ex2(sA[2]);
            float eA3 = ex2(sA[3]);
            float eB0 = ex2(sB[0]);
            float eB1 = ex2(sB[1]);
            float eB2 = ex2(sB[2]);
            float eB3 = ex2(sB[3]);
            unsigned a0 = bf16x2pack(eA1, eA0);
            unsigned a1 = bf16x2pack(eA3, eA2);
            unsigned a2 = bf16x2pack(eB1, eB0);
            unsigned a3 = bf16x2pack(eB3, eB2);

            mma16(lcc, a0, a1, a2, a3, ONES16, ONES16);

            unsigned vk = vbuf + ((c*8) << 2);
#pragma unroll
            for (int j = 0; j < 4; j++) {
                unsigned bb0, bb1, bb2, bb3;
                asm volatile(
                    "ldmatrix.sync.aligned.m8n8.x4.shared.b16 {%0,%1,%2,%3}, [%4];"
                    : "=r"(bb0), "=r"(bb1), "=r"(bb2), "=r"(bb3)
                    : "r"(vk + (unsigned)(j*16*VS*4)));
                mma16(cacc[2*j    ], a0, a1, a2, a3, bb0, bb1);
                mma16(cacc[2*j + 1], a0, a1, a2, a3, bb2, bb3);
            }
        }
    }

    // full l directly from ones-MMA (no k-split merge needed)
    float lf0 = lcc[0];
    float lf1 = lcc[2];

    // ---- epilogue: out = delta*G/l + ftr, pooling partials ----
    float dlt  = delta[0];
    float inv0 = 1.0f / lf0;
    float inv1 = 1.0f / lf1;
    float ps[8][2], pm[8][2];
#pragma unroll
    for (int nb = 0; nb < 8; nb++) {
        int c0 = nb*8 + q4*2;
        size_t a00 = ((size_t)b*CC + c0)*PP + col0 + j0;
        size_t a01 = a00 + PP;
        size_t a10 = a00 + 8;
        size_t a11 = a01 + 8;
        float o00 = dlt*cacc[nb][0]*inv0 + ftr[a00];
        float o01 = dlt*cacc[nb][1]*inv0 + ftr[a01];
        float o10 = dlt*cacc[nb][2]*inv1 + ftr[a10];
        float o11 = dlt*cacc[nb][3]*inv1 + ftr[a11];
        g_out[a00] = o00; g_out[a01] = o01;
        g_out[a10] = o10; g_out[a11] = o11;
        ps[nb][0] = o00 + o10;  pm[nb][0] = fmaxf(o00, o10);
        ps[nb][1] = o01 + o11;  pm[nb][1] = fmaxf(o01, o11);
    }
#pragma unroll
    for (int nb = 0; nb < 8; nb++)
#pragma unroll
        for (int par = 0; par < 2; par++) {
#pragma unroll
            for (int off = 4; off <= 16; off <<= 1) {
                ps[nb][par] += __shfl_xor_sync(0xffffffffu, ps[nb][par], off);
                pm[nb][par] = fmaxf(pm[nb][par],
                                    __shfl_xor_sync(0xffffffffu, pm[nb][par], off));
            }
        }
    if (r == 0) {
#pragma unroll
        for (int nb = 0; nb < 8; nb++) {
            sm.wsum[jb][nb*8 + q4*2    ] = ps[nb][0];
            sm.wsum[jb][nb*8 + q4*2 + 1] = ps[nb][1];
            sm.wmax[jb][nb*8 + q4*2    ] = pm[nb][0];
            sm.wmax[jb][nb*8 + q4*2 + 1] = pm[nb][1];
        }
    }
    __syncthreads();

    if (tid < 64) {
        float s  = 0.0f;
        float mx = -INFINITY;
#pragma unroll
        for (int g = 0; g < 8; g++) {
            s += sm.wsum[g][tid];
            mx = fmaxf(mx, sm.wmax[g][tid]);
        }
        atomicAdd(&g_sum[b*CC + tid], s);
        atomicMax(&g_maxk[b*CC + tid], fkey(mx));
    }
}

// ---------------- K3: apply gate (per-block gate, parallel layers) -----------
__global__ void final_kernel(float* __restrict__ out,
                             const float* __restrict__ w_avg1, const float* __restrict__ w_avg2,
                             const float* __restrict__ w_max1, const float* __restrict__ w_max2)
{
    __shared__ float hh[32];
    __shared__ float gate_s;
    int t = threadIdx.x;
    int blk = blockIdx.x;
    int b = blk >> 8;
    int c = (blk >> 2) & 63;

    {
        int d = t >> 3, part = t & 7;
        int branch = d >> 4, o = d & 15;
        const float* w1 = branch ? w_max1 : w_avg1;
        float acc = 0.0f;
#pragma unroll
        for (int i = 0; i < 8; i++) {
            int idx = part*8 + i;
            float f = branch ? funkey(g_maxk[b*CC + idx])
                             : g_sum[b*CC + idx] * (1.0f/(float)PP);
            acc += w1[o*64 + idx] * f;
        }
#pragma unroll
        for (int off = 1; off <= 4; off <<= 1)
            acc += __shfl_xor_sync(0xffffffffu, acc, off);
        if (part == 0) hh[d] = fmaxf(acc, 0.0f);
    }
    __syncthreads();
    if (t < 32) {
        int branch = t >> 4, o = t & 15;
        const float* w2 = branch ? w_max2 : w_avg2;
        float v = w2[c*16 + o] * hh[branch*16 + o];
#pragma unroll
        for (int off = 1; off <= 16; off <<= 1)
            v += __shfl_xor_sync(0xffffffffu, v, off);
        if (t == 0) gate_s = 1.0f / (1.0f + __expf(-v));
    }
    __syncthreads();

    float gv = gate_s;
    int base = blk * 256 + t;
    float4 v0 = reinterpret_cast<const float4*>(g_out)[base];
    v0.x *= gv; v0.y *= gv; v0.z *= gv; v0.w *= gv;
    reinterpret_cast<float4*>(out)[base] = v0;
}

// ---------------- launch ------------------------------------------------------
extern "C" void kernel_launch(void* const* d_in, const int* in_sizes, int n_in,
                              void* d_out, int out_size)
{
    const float* ftr    = (const float*)d_in[0];
    const float* wq     = (const float*)d_in[1];
    const float* bq     = (const float*)d_in[2];
    const float* wk     = (const float*)d_in[3];
    const float* bk     = (const float*)d_in[4];
    const float* wv     = (const float*)d_in[5];
    const float* bv     = (const float*)d_in[6];
    const float* delta  = (const float*)d_in[7];
    const float* w_avg1 = (const float*)d_in[8];
    const float* w_avg2 = (const float*)d_in[9];
    const float* w_max1 = (const float*)d_in[10];
    const float* w_max2 = (const float*)d_in[11];
    float* out = (float*)d_out;

    cudaFuncSetAttribute(attn_kernel, cudaFuncAttributeMaxDynamicSharedMemorySize,
                         (int)sizeof(SmemB));

    qkv_kernel<<<dim3(PP/64, BB), 384>>>(ftr, wq, bq, wk, bk, wv, bv);
    attn_kernel<<<dim3(PP/NCOL, BB), 256, sizeof(SmemB)>>>(ftr, delta);
    final_kernel<<<1024, 256>>>(out, w_avg1, w_avg2, w_max1, w_max2);
}